// round 1
// baseline (speedup 1.0000x reference)
#include <cuda_runtime.h>
#include <cuda_bf16.h>
#include <cstdint>

// Problem constants (from reference: BLOCK=32, KB=NB=128, M=4096)
#define MDIM 4096
#define KDIM 4096
#define NDIM 4096
#define BB   32      // block size
#define NBCOLS 128   // N / BB
#define KBROWS 128   // K / BB
#define BM   256     // rows of output tile per CTA
#define THREADS 256
#define XS_LD 33     // padded leading dim for x tile (odd -> conflict-free)
#define WS_LD 36     // padded leading dim for w tile (16B-aligned rows)

// Per-output-column block lists (scratch; allocs are forbidden)
__device__ int g_col_count[NBCOLS];
__device__ int g_col_list[NBCOLS * KBROWS];   // worst case: every row block present

// Deterministic bucketing: thread j scans all nnz in order, collecting blocks
// whose output column == j. Order is stable -> bitwise-deterministic output.
__global__ void bucket_kernel(const int* __restrict__ idx_j, int nnz) {
    int j = threadIdx.x;
    if (j >= NBCOLS) return;
    int cnt = 0;
    for (int n = 0; n < nnz; ++n) {
        if (idx_j[n] == j) {
            g_col_list[j * KBROWS + cnt] = n;
            ++cnt;
        }
    }
    g_col_count[j] = cnt;
}

__global__ __launch_bounds__(THREADS) void bsmm_kernel(
    const float* __restrict__ x,
    const float* __restrict__ w,
    const int*  __restrict__ idx_i,
    float*      __restrict__ y)
{
    __shared__ float xs[BM * XS_LD];   // x tile, [m][k] padded
    __shared__ float ws[BB * WS_LD];   // w block, [k][c] padded

    const int j   = blockIdx.x;          // output block-column
    const int m0  = blockIdx.y * BM;     // output row-tile origin
    const int tid = threadIdx.x;
    const int ct  = tid & 7;             // 8 column groups * 4 cols
    const int mt  = tid >> 3;            // 32 row groups * 8 rows

    float acc[8][4];
    #pragma unroll
    for (int r = 0; r < 8; ++r)
        #pragma unroll
        for (int c = 0; c < 4; ++c) acc[r][c] = 0.0f;

    const int cnt = g_col_count[j];
    const int* lst = &g_col_list[j * KBROWS];

    const float4* X4 = reinterpret_cast<const float4*>(x);

    for (int s = 0; s < cnt; ++s) {
        const int n = lst[s];
        const int i = idx_i[n];

        // ---- stage x tile [BM x 32] (float4 gmem loads, conflict-free STS) ----
        #pragma unroll
        for (int t = 0; t < (BM * BB / 4) / THREADS; ++t) {   // 8 iters
            int idx = tid + t * THREADS;                       // 0..2047
            int m   = idx >> 3;                                // 0..255
            int kq  = idx & 7;                                 // float4 within row
            float4 v = X4[(size_t)(m0 + m) * (KDIM / 4) + i * (BB / 4) + kq];
            int base = m * XS_LD + kq * 4;
            xs[base + 0] = v.x;
            xs[base + 1] = v.y;
            xs[base + 2] = v.z;
            xs[base + 3] = v.w;
        }
        // ---- stage w block [32 x 32] (coalesced, conflict-free) ----
        const float* wn = w + (size_t)n * (BB * BB);
        #pragma unroll
        for (int t = 0; t < (BB * BB) / THREADS; ++t) {        // 4 iters
            int idx = tid + t * THREADS;
            int k   = idx >> 5;
            int c   = idx & 31;
            ws[k * WS_LD + c] = wn[idx];
        }
        __syncthreads();

        // ---- 8m x 4c register-tiled inner product over k=0..31 ----
        #pragma unroll
        for (int k = 0; k < BB; ++k) {
            float4 wv = *reinterpret_cast<const float4*>(&ws[k * WS_LD + ct * 4]);
            float xv[8];
            #pragma unroll
            for (int r = 0; r < 8; ++r)
                xv[r] = xs[(mt * 8 + r) * XS_LD + k];
            #pragma unroll
            for (int r = 0; r < 8; ++r) {
                acc[r][0] = fmaf(xv[r], wv.x, acc[r][0]);
                acc[r][1] = fmaf(xv[r], wv.y, acc[r][1]);
                acc[r][2] = fmaf(xv[r], wv.z, acc[r][2]);
                acc[r][3] = fmaf(xv[r], wv.w, acc[r][3]);
            }
        }
        __syncthreads();
    }

    // ---- write output tile (always: empty columns must be zeroed) ----
    #pragma unroll
    for (int r = 0; r < 8; ++r) {
        float4 v = make_float4(acc[r][0], acc[r][1], acc[r][2], acc[r][3]);
        *reinterpret_cast<float4*>(
            &y[(size_t)(m0 + mt * 8 + r) * NDIM + j * BB + ct * 4]) = v;
    }
}

extern "C" void kernel_launch(void* const* d_in, const int* in_sizes, int n_in,
                              void* d_out, int out_size)
{
    const float* x     = (const float*)d_in[0];
    const float* w     = (const float*)d_in[1];
    const int*   idx_i = (const int*)d_in[2];
    const int*   idx_j = (const int*)d_in[3];
    float*       y     = (float*)d_out;
    const int    nnz   = in_sizes[2];

    bucket_kernel<<<1, NBCOLS>>>(idx_j, nnz);

    dim3 grid(NBCOLS, MDIM / BM);
    bsmm_kernel<<<grid, THREADS>>>(x, w, idx_i, y);
}

// round 3
// speedup vs baseline: 1.1976x; 1.1976x over previous
#include <cuda_runtime.h>
#include <cuda_bf16.h>
#include <cstdint>

// Problem constants
#define MDIM 4096
#define KDIM 4096
#define NDIM 4096
#define BB   32
#define NBCOLS 128
#define KBROWS 128
#define BM   256          // rows per CTA
#define THREADS 256
#define XPITCH 80         // bytes per 32-col bf16 row in smem (conflict-free LDSM)
#define MAXBLK (KBROWS * NBCOLS)

// ---------------- device scratch (allocs forbidden) ----------------
__device__ int g_cnt[NBCOLS];
__device__ int g_list[NBCOLS * KBROWS];
// transposed bf16 hi/lo weights: wT[n][c][k], packed 32*32 per block
__device__ __nv_bfloat16 g_wTh[MAXBLK * BB * BB];
__device__ __nv_bfloat16 g_wTl[MAXBLK * BB * BB];

__device__ __forceinline__ uint32_t smem_u32(const void* p) {
    uint32_t a;
    asm("{ .reg .u64 t; cvta.to.shared.u64 t, %1; cvt.u32.u64 %0, t; }" : "=r"(a) : "l"(p));
    return a;
}

// ---------------- bucketing: per-column ordered block list ----------------
__global__ void bucket_kernel(const int* __restrict__ idx_j, int nnz) {
    int j = threadIdx.x;
    if (j >= NBCOLS) return;
    int cnt = 0;
    for (int n = 0; n < nnz; ++n)
        if (idx_j[n] == j) g_list[j * KBROWS + cnt++] = n;
    g_cnt[j] = cnt;
}

// ---------------- w transpose + bf16 hi/lo split (one block per nnz) ----------------
__global__ void wconv_kernel(const float* __restrict__ w) {
    __shared__ float ws[BB][BB + 1];
    const int n = blockIdx.x;
    const int tid = threadIdx.x;
    const float* wn = w + (size_t)n * (BB * BB);
    #pragma unroll
    for (int q = 0; q < 4; ++q) {
        int el = tid + q * THREADS;
        ws[el >> 5][el & 31] = wn[el];
    }
    __syncthreads();
    #pragma unroll
    for (int q = 0; q < 4; ++q) {
        int el = tid + q * THREADS;          // out index: c*32 + k
        int c = el >> 5, k = el & 31;
        float v = ws[k][c];
        __nv_bfloat16 h = __float2bfloat16_rn(v);
        __nv_bfloat16 l = __float2bfloat16_rn(v - __bfloat162float(h));
        g_wTh[(size_t)n * 1024 + el] = h;
        g_wTl[(size_t)n * 1024 + el] = l;
    }
}

// ---------------- main HMMA kernel ----------------
__global__ __launch_bounds__(THREADS, 2) void bsmm_mma_kernel(
    const float* __restrict__ x,
    const int*  __restrict__ idx_i,
    float*      __restrict__ y)
{
    __shared__ __align__(16) char sxh[BM * XPITCH];   // 20 KB
    __shared__ __align__(16) char sxl[BM * XPITCH];   // 20 KB

    const int j    = blockIdx.x;
    const int m0   = blockIdx.y * BM;
    const int tid  = threadIdx.x;
    const int wid  = tid >> 5;
    const int lane = tid & 31;
    const int gid  = lane >> 2;   // groupID
    const int tig  = lane & 3;    // thread-in-group

    // ldmatrix per-lane address pieces: lane -> (matrix, row-in-8)
    const int lrow = lane & 7;
    const int lm   = lane >> 3;                 // matrix 0..3
    const int ld_row_off = ((lm & 1) * 8 + lrow) * XPITCH + (lm >> 1) * 16;
    const uint32_t xh_base = smem_u32(sxh);
    const uint32_t xl_base = smem_u32(sxl);

    float acc[2][4][4];   // [stripe][ntile][reg]
    #pragma unroll
    for (int s = 0; s < 2; ++s)
        #pragma unroll
        for (int t = 0; t < 4; ++t)
            #pragma unroll
            for (int r = 0; r < 4; ++r) acc[s][t][r] = 0.0f;

    const int cnt = g_cnt[j];
    const int* lst = &g_list[j * KBROWS];
    const float4* X4 = reinterpret_cast<const float4*>(x);

    for (int e = 0; e < cnt; ++e) {
        const int n = lst[e];
        const int i = idx_i[n];

        // ---- stage x tile [256 x 32]: fp32 -> bf16 hi/lo into smem ----
        #pragma unroll
        for (int t = 0; t < 8; ++t) {
            int idx = tid + t * THREADS;          // 0..2047 float4 chunks
            int row = idx >> 3;
            int c4  = idx & 7;
            float4 v = X4[(size_t)(m0 + row) * (KDIM / 4) + i * (BB / 4) + c4];
            __nv_bfloat162 h01 = __float22bfloat162_rn(make_float2(v.x, v.y));
            __nv_bfloat162 h23 = __float22bfloat162_rn(make_float2(v.z, v.w));
            float2 r01 = make_float2(v.x - __bfloat162float(__low2bfloat16(h01)),
                                     v.y - __bfloat162float(__high2bfloat16(h01)));
            float2 r23 = make_float2(v.z - __bfloat162float(__low2bfloat16(h23)),
                                     v.w - __bfloat162float(__high2bfloat16(h23)));
            __nv_bfloat162 l01 = __float22bfloat162_rn(r01);
            __nv_bfloat162 l23 = __float22bfloat162_rn(r23);
            uint32_t off = row * XPITCH + c4 * 8;
            uint2 hv, lv;
            hv.x = *reinterpret_cast<uint32_t*>(&h01);
            hv.y = *reinterpret_cast<uint32_t*>(&h23);
            lv.x = *reinterpret_cast<uint32_t*>(&l01);
            lv.y = *reinterpret_cast<uint32_t*>(&l23);
            *reinterpret_cast<uint2*>(sxh + off) = hv;
            *reinterpret_cast<uint2*>(sxl + off) = lv;
        }
        __syncthreads();

        // ---- compute: 3-term bf16 split on HMMA ----
        const uint32_t* wTh = reinterpret_cast<const uint32_t*>(g_wTh + (size_t)n * 1024);
        const uint32_t* wTl = reinterpret_cast<const uint32_t*>(g_wTl + (size_t)n * 1024);

        #pragma unroll
        for (int kc = 0; kc < 2; ++kc) {
            // A fragments for both 16-row stripes, hi and lo
            uint32_t ah[2][4], al[2][4];
            #pragma unroll
            for (int s = 0; s < 2; ++s) {
                uint32_t row_base = (wid * 32 + s * 16) * XPITCH + kc * 32;
                uint32_t ha = xh_base + row_base + ld_row_off;
                uint32_t la = xl_base + row_base + ld_row_off;
                asm volatile("ldmatrix.sync.aligned.m8n8.x4.shared.b16 {%0,%1,%2,%3}, [%4];"
                             : "=r"(ah[s][0]), "=r"(ah[s][1]), "=r"(ah[s][2]), "=r"(ah[s][3])
                             : "r"(ha));
                asm volatile("ldmatrix.sync.aligned.m8n8.x4.shared.b16 {%0,%1,%2,%3}, [%4];"
                             : "=r"(al[s][0]), "=r"(al[s][1]), "=r"(al[s][2]), "=r"(al[s][3])
                             : "r"(la));
            }
            #pragma unroll
            for (int nt = 0; nt < 4; ++nt) {
                // B fragments: wT[c][k], c = nt*8+gid, b0 at k=kc*16+2tig, b1 +8
                int boff = (nt * 8 + gid) * (BB / 2) + kc * 8 + tig;  // u32 index
                uint32_t bh0 = wTh[boff], bh1 = wTh[boff + 4];
                uint32_t bl0 = wTl[boff], bl1 = wTl[boff + 4];
                #pragma unroll
                for (int s = 0; s < 2; ++s) {
                    float* d = acc[s][nt];
                    asm volatile(
                        "mma.sync.aligned.m16n8k16.row.col.f32.bf16.bf16.f32 "
                        "{%0,%1,%2,%3}, {%4,%5,%6,%7}, {%8,%9}, {%0,%1,%2,%3};"
                        : "+f"(d[0]), "+f"(d[1]), "+f"(d[2]), "+f"(d[3])
                        : "r"(ah[s][0]), "r"(ah[s][1]), "r"(ah[s][2]), "r"(ah[s][3]),
                          "r"(bh0), "r"(bh1));
                    asm volatile(
                        "mma.sync.aligned.m16n8k16.row.col.f32.bf16.bf16.f32 "
                        "{%0,%1,%2,%3}, {%4,%5,%6,%7}, {%8,%9}, {%0,%1,%2,%3};"
                        : "+f"(d[0]), "+f"(d[1]), "+f"(d[2]), "+f"(d[3])
                        : "r"(al[s][0]), "r"(al[s][1]), "r"(al[s][2]), "r"(al[s][3]),
                          "r"(bh0), "r"(bh1));
                    asm volatile(
                        "mma.sync.aligned.m16n8k16.row.col.f32.bf16.bf16.f32 "
                        "{%0,%1,%2,%3}, {%4,%5,%6,%7}, {%8,%9}, {%0,%1,%2,%3};"
                        : "+f"(d[0]), "+f"(d[1]), "+f"(d[2]), "+f"(d[3])
                        : "r"(ah[s][0]), "r"(ah[s][1]), "r"(ah[s][2]), "r"(ah[s][3]),
                          "r"(bl0), "r"(bl1));
                }
            }
        }
        __syncthreads();
    }

    // ---- epilogue: write 256x32 tile (zeros included for empty columns) ----
    #pragma unroll
    for (int s = 0; s < 2; ++s) {
        #pragma unroll
        for (int nt = 0; nt < 4; ++nt) {
            const float* d = acc[s][nt];
            int row0 = m0 + wid * 32 + s * 16 + gid;
            int col  = j * BB + nt * 8 + tig * 2;
            *reinterpret_cast<float2*>(&y[(size_t)row0 * NDIM + col]) =
                make_float2(d[0], d[1]);
            *reinterpret_cast<float2*>(&y[(size_t)(row0 + 8) * NDIM + col]) =
                make_float2(d[2], d[3]);
        }
    }
}

extern "C" void kernel_launch(void* const* d_in, const int* in_sizes, int n_in,
                              void* d_out, int out_size)
{
    const float* x     = (const float*)d_in[0];
    const float* w     = (const float*)d_in[1];
    const int*   idx_i = (const int*)d_in[2];
    const int*   idx_j = (const int*)d_in[3];
    float*       y     = (float*)d_out;
    const int    nnz   = in_sizes[2];

    bucket_kernel<<<1, NBCOLS>>>(idx_j, nnz);
    wconv_kernel<<<nnz, THREADS>>>(w);

    dim3 grid(NBCOLS, MDIM / BM);
    bsmm_mma_kernel<<<grid, THREADS>>>(x, idx_i, y);
}

// round 4
// speedup vs baseline: 1.2584x; 1.0507x over previous
#include <cuda_runtime.h>
#include <cuda_bf16.h>
#include <cstdint>

#define MDIM 4096
#define KDIM 4096
#define NDIM 4096
#define BB   32
#define NBCOLS 128
#define KBROWS 128
#define BM   256
#define THREADS 256
#define XPITCH 64               // bytes per 32-col bf16 row in smem (conflict-free)
#define MAXBLK (KBROWS * NBCOLS)

// ---------------- device scratch ----------------
__device__ int g_cnt[NBCOLS];
__device__ int g_listn[NBCOLS * KBROWS];          // block index
__device__ int g_listi[NBCOLS * KBROWS];          // block-row i
// transposed bf16 hi/lo weights: wT[n][c][k]
__device__ __nv_bfloat16 g_wTh[MAXBLK * BB * BB];
__device__ __nv_bfloat16 g_wTl[MAXBLK * BB * BB];
// pre-tiled bf16 hi/lo x: [kblock][M][32]
__device__ __nv_bfloat16 g_xh[(size_t)KBROWS * MDIM * BB];
__device__ __nv_bfloat16 g_xl[(size_t)KBROWS * MDIM * BB];

__device__ __forceinline__ uint32_t smem_u32(const void* p) {
    uint32_t a;
    asm("{ .reg .u64 t; cvta.to.shared.u64 t, %1; cvt.u32.u64 %0, t; }" : "=r"(a) : "l"(p));
    return a;
}

// ---------------- parallel bucket: one warp per output column ----------------
__global__ void bucket_kernel(const int* __restrict__ idx_i,
                              const int* __restrict__ idx_j, int nnz) {
    const int j    = blockIdx.x * (blockDim.x >> 5) + (threadIdx.x >> 5);
    const int lane = threadIdx.x & 31;
    if (j >= NBCOLS) return;
    int cnt = 0;
    for (int base = 0; base < nnz; base += 32) {
        int n = base + lane;
        bool hit = (n < nnz) && (idx_j[n] == j);
        unsigned m = __ballot_sync(0xFFFFFFFFu, hit);
        if (hit) {
            int pos = cnt + __popc(m & ((1u << lane) - 1u));
            g_listn[j * KBROWS + pos] = n;
            g_listi[j * KBROWS + pos] = idx_i[n];
        }
        cnt += __popc(m);
    }
    if (lane == 0) g_cnt[j] = cnt;
}

// ---------------- x pre-convert: fp32 -> bf16 hi/lo, tiled [i][m][32] ----------------
__global__ __launch_bounds__(THREADS) void xconv_kernel(const float* __restrict__ x) {
    // each thread handles 4 consecutive k within one (i, m) row chunk
    size_t o4 = (size_t)blockIdx.x * THREADS + threadIdx.x;   // float4-granular
    // total float4 units: 128*4096*32/4 = 4,194,304
    int kq = (int)(o4 & 7);              // which float4 within 32-k row
    int m  = (int)((o4 >> 3) & 4095);
    int i  = (int)(o4 >> 15);
    float4 v = reinterpret_cast<const float4*>(x)[(size_t)m * (KDIM / 4) + i * 8 + kq];
    __nv_bfloat162 h01 = __float22bfloat162_rn(make_float2(v.x, v.y));
    __nv_bfloat162 h23 = __float22bfloat162_rn(make_float2(v.z, v.w));
    float2 r01 = make_float2(v.x - __bfloat162float(__low2bfloat16(h01)),
                             v.y - __bfloat162float(__high2bfloat16(h01)));
    float2 r23 = make_float2(v.z - __bfloat162float(__low2bfloat16(h23)),
                             v.w - __bfloat162float(__high2bfloat16(h23)));
    __nv_bfloat162 l01 = __float22bfloat162_rn(r01);
    __nv_bfloat162 l23 = __float22bfloat162_rn(r23);
    uint2 hv, lv;
    hv.x = *reinterpret_cast<uint32_t*>(&h01);
    hv.y = *reinterpret_cast<uint32_t*>(&h23);
    lv.x = *reinterpret_cast<uint32_t*>(&l01);
    lv.y = *reinterpret_cast<uint32_t*>(&l23);
    reinterpret_cast<uint2*>(g_xh)[o4] = hv;
    reinterpret_cast<uint2*>(g_xl)[o4] = lv;
}

// ---------------- w transpose + bf16 hi/lo split ----------------
__global__ void wconv_kernel(const float* __restrict__ w) {
    __shared__ float ws[BB][BB + 1];
    const int n = blockIdx.x;
    const int tid = threadIdx.x;
    const float* wn = w + (size_t)n * (BB * BB);
    #pragma unroll
    for (int q = 0; q < 4; ++q) {
        int el = tid + q * THREADS;
        ws[el >> 5][el & 31] = wn[el];
    }
    __syncthreads();
    #pragma unroll
    for (int q = 0; q < 4; ++q) {
        int el = tid + q * THREADS;          // out index: c*32 + k
        int c = el >> 5, k = el & 31;
        float v = ws[k][c];
        __nv_bfloat16 h = __float2bfloat16_rn(v);
        __nv_bfloat16 l = __float2bfloat16_rn(v - __bfloat162float(h));
        g_wTh[(size_t)n * 1024 + el] = h;
        g_wTl[(size_t)n * 1024 + el] = l;
    }
}

// ---------------- main HMMA kernel ----------------
__global__ __launch_bounds__(THREADS) void bsmm_mma_kernel(
    const int* __restrict__ dummy,
    float*     __restrict__ y)
{
    __shared__ __align__(16) char sxh[BM * XPITCH];   // 16 KB
    __shared__ __align__(16) char sxl[BM * XPITCH];   // 16 KB

    const int j    = blockIdx.x;
    const int m0   = blockIdx.y * BM;
    const int tid  = threadIdx.x;
    const int wid  = tid >> 5;
    const int lane = tid & 31;
    const int gid  = lane >> 2;
    const int tig  = lane & 3;

    const int lrow = lane & 7;
    const int lm   = lane >> 3;
    const int ld_row_off = ((lm & 1) * 8 + lrow) * XPITCH + (lm >> 1) * 16;
    const uint32_t xh_base = smem_u32(sxh);
    const uint32_t xl_base = smem_u32(sxl);

    float acc[2][4][4];
    #pragma unroll
    for (int s = 0; s < 2; ++s)
        #pragma unroll
        for (int t = 0; t < 4; ++t)
            #pragma unroll
            for (int r = 0; r < 4; ++r) acc[s][t][r] = 0.0f;

    const int cnt = g_cnt[j];
    const int* lstn = &g_listn[j * KBROWS];
    const int* lsti = &g_listi[j * KBROWS];

    for (int e = 0; e < cnt; ++e) {
        const int n = lstn[e];
        const int i = lsti[e];

        // ---- stage: linear 16KB copies of pre-converted bf16 tiles ----
        const float4* H4 = reinterpret_cast<const float4*>(
            g_xh + ((size_t)i * MDIM + m0) * BB);
        const float4* L4 = reinterpret_cast<const float4*>(
            g_xl + ((size_t)i * MDIM + m0) * BB);
        float4* SH = reinterpret_cast<float4*>(sxh);
        float4* SL = reinterpret_cast<float4*>(sxl);
        #pragma unroll
        for (int t = 0; t < 4; ++t) {
            SH[tid + t * THREADS] = H4[tid + t * THREADS];
            SL[tid + t * THREADS] = L4[tid + t * THREADS];
        }
        __syncthreads();

        // ---- compute: 3-term bf16 split on HMMA ----
        const uint32_t* wTh = reinterpret_cast<const uint32_t*>(g_wTh + (size_t)n * 1024);
        const uint32_t* wTl = reinterpret_cast<const uint32_t*>(g_wTl + (size_t)n * 1024);

        #pragma unroll
        for (int kc = 0; kc < 2; ++kc) {
            uint32_t ah[2][4], al[2][4];
            #pragma unroll
            for (int s = 0; s < 2; ++s) {
                uint32_t row_base = (wid * 32 + s * 16) * XPITCH + kc * 32;
                uint32_t ha = xh_base + row_base + ld_row_off;
                uint32_t la = xl_base + row_base + ld_row_off;
                asm volatile("ldmatrix.sync.aligned.m8n8.x4.shared.b16 {%0,%1,%2,%3}, [%4];"
                             : "=r"(ah[s][0]), "=r"(ah[s][1]), "=r"(ah[s][2]), "=r"(ah[s][3])
                             : "r"(ha));
                asm volatile("ldmatrix.sync.aligned.m8n8.x4.shared.b16 {%0,%1,%2,%3}, [%4];"
                             : "=r"(al[s][0]), "=r"(al[s][1]), "=r"(al[s][2]), "=r"(al[s][3])
                             : "r"(la));
            }
            #pragma unroll
            for (int nt = 0; nt < 4; ++nt) {
                int boff = (nt * 8 + gid) * (BB / 2) + kc * 8 + tig;
                uint32_t bh0 = wTh[boff], bh1 = wTh[boff + 4];
                uint32_t bl0 = wTl[boff], bl1 = wTl[boff + 4];
                #pragma unroll
                for (int s = 0; s < 2; ++s) {
                    float* d = acc[s][nt];
                    asm volatile(
                        "mma.sync.aligned.m16n8k16.row.col.f32.bf16.bf16.f32 "
                        "{%0,%1,%2,%3}, {%4,%5,%6,%7}, {%8,%9}, {%0,%1,%2,%3};"
                        : "+f"(d[0]), "+f"(d[1]), "+f"(d[2]), "+f"(d[3])
                        : "r"(ah[s][0]), "r"(ah[s][1]), "r"(ah[s][2]), "r"(ah[s][3]),
                          "r"(bh0), "r"(bh1));
                    asm volatile(
                        "mma.sync.aligned.m16n8k16.row.col.f32.bf16.bf16.f32 "
                        "{%0,%1,%2,%3}, {%4,%5,%6,%7}, {%8,%9}, {%0,%1,%2,%3};"
                        : "+f"(d[0]), "+f"(d[1]), "+f"(d[2]), "+f"(d[3])
                        : "r"(al[s][0]), "r"(al[s][1]), "r"(al[s][2]), "r"(al[s][3]),
                          "r"(bh0), "r"(bh1));
                    asm volatile(
                        "mma.sync.aligned.m16n8k16.row.col.f32.bf16.bf16.f32 "
                        "{%0,%1,%2,%3}, {%4,%5,%6,%7}, {%8,%9}, {%0,%1,%2,%3};"
                        : "+f"(d[0]), "+f"(d[1]), "+f"(d[2]), "+f"(d[3])
                        : "r"(ah[s][0]), "r"(ah[s][1]), "r"(ah[s][2]), "r"(ah[s][3]),
                          "r"(bl0), "r"(bl1));
                }
            }
        }
        __syncthreads();
    }

    // ---- epilogue ----
    #pragma unroll
    for (int s = 0; s < 2; ++s) {
        #pragma unroll
        for (int nt = 0; nt < 4; ++nt) {
            const float* d = acc[s][nt];
            int row0 = m0 + wid * 32 + s * 16 + gid;
            int col  = j * BB + nt * 8 + tig * 2;
            *reinterpret_cast<float2*>(&y[(size_t)row0 * NDIM + col]) =
                make_float2(d[0], d[1]);
            *reinterpret_cast<float2*>(&y[(size_t)(row0 + 8) * NDIM + col]) =
                make_float2(d[2], d[3]);
        }
    }
}

extern "C" void kernel_launch(void* const* d_in, const int* in_sizes, int n_in,
                              void* d_out, int out_size)
{
    const float* x     = (const float*)d_in[0];
    const float* w     = (const float*)d_in[1];
    const int*   idx_i = (const int*)d_in[2];
    const int*   idx_j = (const int*)d_in[3];
    float*       y     = (float*)d_out;
    const int    nnz   = in_sizes[2];

    bucket_kernel<<<16, 256>>>(idx_i, idx_j, nnz);
    // 128*4096*32/4 float4 units / 256 threads = 16384 blocks
    xconv_kernel<<<16384, THREADS>>>(x);
    wconv_kernel<<<nnz, THREADS>>>(w);

    dim3 grid(NBCOLS, MDIM / BM);
    bsmm_mma_kernel<<<grid, THREADS>>>(nullptr, y);
}

// round 6
// speedup vs baseline: 2.3613x; 1.8765x over previous
#include <cuda_runtime.h>
#include <cuda_bf16.h>
#include <cstdint>

#define MDIM 4096
#define KDIM 4096
#define NDIM 4096
#define BB   32
#define NBCOLS 128
#define KBROWS 128
#define BM   256
#define THREADS 256
#define MAXBLK (KBROWS * NBCOLS)

// ---------------- device scratch ----------------
__device__ int g_cnt[NBCOLS];
__device__ int g_listn[NBCOLS * KBROWS];
__device__ int g_listi[NBCOLS * KBROWS];
// w in HMMA fragment order: per block, 512 u32 hi + 512 u32 lo
// index: hi/lo*512 + ((kc*2+reg)*4 + nt)*32 + lane
__device__ uint32_t g_wfrag[(size_t)MAXBLK * 1024];
// pre-tiled bf16 hi/lo x: [kblock][M][32]
__device__ __nv_bfloat16 g_xh[(size_t)KBROWS * MDIM * BB];
__device__ __nv_bfloat16 g_xl[(size_t)KBROWS * MDIM * BB];

__device__ __forceinline__ uint32_t smem_u32(const void* p) {
    uint32_t a;
    asm("{ .reg .u64 t; cvta.to.shared.u64 t, %1; cvt.u32.u64 %0, t; }" : "=r"(a) : "l"(p));
    return a;
}

// ---------------- parallel bucket: one warp per output column ----------------
__global__ void bucket_kernel(const int* __restrict__ idx_i,
                              const int* __restrict__ idx_j, int nnz) {
    const int j    = blockIdx.x * (blockDim.x >> 5) + (threadIdx.x >> 5);
    const int lane = threadIdx.x & 31;
    if (j >= NBCOLS) return;
    int cnt = 0;
    for (int base = 0; base < nnz; base += 32) {
        int n = base + lane;
        bool hit = (n < nnz) && (idx_j[n] == j);
        unsigned m = __ballot_sync(0xFFFFFFFFu, hit);
        if (hit) {
            int pos = cnt + __popc(m & ((1u << lane) - 1u));
            g_listn[j * KBROWS + pos] = n;
            g_listi[j * KBROWS + pos] = idx_i[n];
        }
        cnt += __popc(m);
    }
    if (lane == 0) g_cnt[j] = cnt;
}

// ---------------- x pre-convert: fp32 -> bf16 hi/lo, tiled [i][m][32] ----------------
__global__ __launch_bounds__(THREADS) void xconv_kernel(const float* __restrict__ x) {
    size_t o4 = (size_t)blockIdx.x * THREADS + threadIdx.x;   // float4-granular
    int kq = (int)(o4 & 7);
    int m  = (int)((o4 >> 3) & 4095);
    int i  = (int)(o4 >> 15);
    float4 v = reinterpret_cast<const float4*>(x)[(size_t)m * (KDIM / 4) + i * 8 + kq];
    __nv_bfloat162 h01 = __float22bfloat162_rn(make_float2(v.x, v.y));
    __nv_bfloat162 h23 = __float22bfloat162_rn(make_float2(v.z, v.w));
    float2 r01 = make_float2(v.x - __bfloat162float(__low2bfloat16(h01)),
                             v.y - __bfloat162float(__high2bfloat16(h01)));
    float2 r23 = make_float2(v.z - __bfloat162float(__low2bfloat16(h23)),
                             v.w - __bfloat162float(__high2bfloat16(h23)));
    __nv_bfloat162 l01 = __float22bfloat162_rn(r01);
    __nv_bfloat162 l23 = __float22bfloat162_rn(r23);
    uint2 hv, lv;
    hv.x = *reinterpret_cast<uint32_t*>(&h01);
    hv.y = *reinterpret_cast<uint32_t*>(&h23);
    lv.x = *reinterpret_cast<uint32_t*>(&l01);
    lv.y = *reinterpret_cast<uint32_t*>(&l23);
    reinterpret_cast<uint2*>(g_xh)[o4] = hv;
    reinterpret_cast<uint2*>(g_xl)[o4] = lv;
}

// ---------------- w -> HMMA fragment order, bf16 hi/lo ----------------
__global__ void wconv_kernel(const float* __restrict__ w) {
    __shared__ float ws[BB * BB];     // w[n] as [k][c]
    const int n = blockIdx.x;
    const int tid = threadIdx.x;
    const float* wn = w + (size_t)n * (BB * BB);
    #pragma unroll
    for (int q = 0; q < 4; ++q) ws[tid + q * THREADS] = wn[tid + q * THREADS];
    __syncthreads();
    #pragma unroll
    for (int q = 0; q < 4; ++q) {
        int oi   = tid + q * THREADS;        // 0..1023
        int hilo = oi >> 9;                  // 0 = hi, 1 = lo
        int rem  = oi & 511;
        int lane = rem & 31;
        int nt   = (rem >> 5) & 3;
        int reg  = (rem >> 7) & 1;
        int kc   = rem >> 8;
        int gid  = lane >> 2, tig = lane & 3;
        int c  = nt * 8 + gid;
        int k0 = kc * 16 + 2 * tig + reg * 8;
        float f0 = ws[k0 * BB + c];
        float f1 = ws[(k0 + 1) * BB + c];
        __nv_bfloat16 h0 = __float2bfloat16_rn(f0);
        __nv_bfloat16 h1 = __float2bfloat16_rn(f1);
        __nv_bfloat162 out;
        if (hilo == 0) {
            out = __nv_bfloat162(h0, h1);
        } else {
            out = __float22bfloat162_rn(make_float2(f0 - __bfloat162float(h0),
                                                    f1 - __bfloat162float(h1)));
        }
        g_wfrag[(size_t)n * 1024 + oi] = *reinterpret_cast<uint32_t*>(&out);
    }
}

// ---------------- main HMMA kernel ----------------
// x smem: 64B rows, 16B chunks XOR-swizzled: chunk' = (chunk + (row>>1)) & 3
__global__ __launch_bounds__(THREADS) void bsmm_mma_kernel(float* __restrict__ y)
{
    __shared__ __align__(16) char sxh[BM * 64];   // 16 KB
    __shared__ __align__(16) char sxl[BM * 64];   // 16 KB

    const int j    = blockIdx.x;
    const int m0   = blockIdx.y * BM;
    const int tid  = threadIdx.x;
    const int wid  = tid >> 5;
    const int lane = tid & 31;
    const int gid  = lane >> 2;
    const int tig  = lane & 3;

    const int lrow = lane & 7;
    const int lm   = lane >> 3;
    const uint32_t xh_base = smem_u32(sxh);
    const uint32_t xl_base = smem_u32(sxl);

    // per-lane ldmatrix row (within CTA tile) for each 16-row stripe
    const int R0 = wid * 32 + (lm & 1) * 8 + lrow;       // stripe s adds s*16
    const int chunk_half = lm >> 1;                      // 16B half within 32B k-group

    float acc[2][4][4];
    #pragma unroll
    for (int s = 0; s < 2; ++s)
        #pragma unroll
        for (int t = 0; t < 4; ++t)
            #pragma unroll
            for (int r = 0; r < 4; ++r) acc[s][t][r] = 0.0f;

    const int cnt = g_cnt[j];
    const int* lstn = &g_listn[j * KBROWS];
    const int* lsti = &g_listi[j * KBROWS];

    // staging indices: thread handles 4 float4 per array
    int st_r[4], st_off[4];
    #pragma unroll
    for (int t = 0; t < 4; ++t) {
        int idx = tid + t * THREADS;         // 0..1023
        int r = idx >> 2, c = idx & 3;
        st_r[t]   = idx;
        st_off[t] = r * 64 + (((c + (r >> 1)) & 3) << 4);
    }

    for (int e = 0; e < cnt; ++e) {
        const int n = lstn[e];
        const int i = lsti[e];

        // ---- stage x tiles via cp.async (swizzled, conflict-free) ----
        const char* Hg = reinterpret_cast<const char*>(
            g_xh + ((size_t)i * MDIM + m0) * BB);
        const char* Lg = reinterpret_cast<const char*>(
            g_xl + ((size_t)i * MDIM + m0) * BB);
        #pragma unroll
        for (int t = 0; t < 4; ++t) {
            asm volatile("cp.async.cg.shared.global [%0], [%1], 16;"
                         :: "r"(xh_base + st_off[t]), "l"(Hg + st_r[t] * 16));
            asm volatile("cp.async.cg.shared.global [%0], [%1], 16;"
                         :: "r"(xl_base + st_off[t]), "l"(Lg + st_r[t] * 16));
        }
        asm volatile("cp.async.commit_group;");
        asm volatile("cp.async.wait_group 0;");
        __syncthreads();

        const uint32_t* wf = g_wfrag + ((size_t)n << 10);

        #pragma unroll
        for (int kc = 0; kc < 2; ++kc) {
            uint32_t ah[2][4], al[2][4];
            #pragma unroll
            for (int s = 0; s < 2; ++s) {
                int R = R0 + s * 16;
                int chunk = kc * 2 + chunk_half;
                uint32_t off = R * 64 + (((chunk + (R >> 1)) & 3) << 4);
                uint32_t ha = xh_base + off;
                uint32_t la = xl_base + off;
                asm volatile("ldmatrix.sync.aligned.m8n8.x4.shared.b16 {%0,%1,%2,%3}, [%4];"
                             : "=r"(ah[s][0]), "=r"(ah[s][1]), "=r"(ah[s][2]), "=r"(ah[s][3])
                             : "r"(ha));
                asm volatile("ldmatrix.sync.aligned.m8n8.x4.shared.b16 {%0,%1,%2,%3}, [%4];"
                             : "=r"(al[s][0]), "=r"(al[s][1]), "=r"(al[s][2]), "=r"(al[s][3])
                             : "r"(la));
            }
            #pragma unroll
            for (int nt = 0; nt < 4; ++nt) {
                uint32_t bh0 = wf[((kc * 2 + 0) * 4 + nt) * 32 + lane];
                uint32_t bh1 = wf[((kc * 2 + 1) * 4 + nt) * 32 + lane];
                uint32_t bl0 = wf[512 + ((kc * 2 + 0) * 4 + nt) * 32 + lane];
                uint32_t bl1 = wf[512 + ((kc * 2 + 1) * 4 + nt) * 32 + lane];
                #pragma unroll
                for (int s = 0; s < 2; ++s) {
                    float* d = acc[s][nt];
                    asm volatile(
                        "mma.sync.aligned.m16n8k16.row.col.f32.bf16.bf16.f32 "
                        "{%0,%1,%2,%3}, {%4,%5,%6,%7}, {%8,%9}, {%0,%1,%2,%3};"
                        : "+f"(d[0]), "+f"(d[1]), "+f"(d[2]), "+f"(d[3])
                        : "r"(ah[s][0]), "r"(ah[s][1]), "r"(ah[s][2]), "r"(ah[s][3]),
                          "r"(bh0), "r"(bh1));
                    asm volatile(
                        "mma.sync.aligned.m16n8k16.row.col.f32.bf16.bf16.f32 "
                        "{%0,%1,%2,%3}, {%4,%5,%6,%7}, {%8,%9}, {%0,%1,%2,%3};"
                        : "+f"(d[0]), "+f"(d[1]), "+f"(d[2]), "+f"(d[3])
                        : "r"(al[s][0]), "r"(al[s][1]), "r"(al[s][2]), "r"(al[s][3]),
                          "r"(bh0), "r"(bh1));
                    asm volatile(
                        "mma.sync.aligned.m16n8k16.row.col.f32.bf16.bf16.f32 "
                        "{%0,%1,%2,%3}, {%4,%5,%6,%7}, {%8,%9}, {%0,%1,%2,%3};"
                        : "+f"(d[0]), "+f"(d[1]), "+f"(d[2]), "+f"(d[3])
                        : "r"(ah[s][0]), "r"(ah[s][1]), "r"(ah[s][2]), "r"(ah[s][3]),
                          "r"(bl0), "r"(bl1));
                }
            }
        }
        __syncthreads();
    }

    // ---- epilogue ----
    #pragma unroll
    for (int s = 0; s < 2; ++s) {
        #pragma unroll
        for (int nt = 0; nt < 4; ++nt) {
            const float* d = acc[s][nt];
            int row0 = m0 + wid * 32 + s * 16 + gid;
            int col  = j * BB + nt * 8 + tig * 2;
            *reinterpret_cast<float2*>(&y[(size_t)row0 * NDIM + col]) =
                make_float2(d[0], d[1]);
            *reinterpret_cast<float2*>(&y[(size_t)(row0 + 8) * NDIM + col]) =
                make_float2(d[2], d[3]);
        }
    }
}

extern "C" void kernel_launch(void* const* d_in, const int* in_sizes, int n_in,
                              void* d_out, int out_size)
{
    const float* x     = (const float*)d_in[0];
    const float* w     = (const float*)d_in[1];
    const int*   idx_i = (const int*)d_in[2];
    const int*   idx_j = (const int*)d_in[3];
    float*       y     = (float*)d_out;
    const int    nnz   = in_sizes[2];

    bucket_kernel<<<16, 256>>>(idx_i, idx_j, nnz);
    xconv_kernel<<<16384, THREADS>>>(x);
    wconv_kernel<<<nnz, THREADS>>>(w);

    dim3 grid(NBCOLS, MDIM / BM);
    bsmm_mma_kernel<<<grid, THREADS>>>(y);
}